// round 5
// baseline (speedup 1.0000x reference)
#include <cuda_runtime.h>
#include <cstdint>

// Problem constants
#define Bn    32768
#define Gn    25
#define INn   128
#define NCn   3
#define OUTn  75
#define ROWF  (Gn * INn)              // 3200 floats per x row
#define ROWB  (ROWF * 4)              // 12800 bytes per row

#define ROWS_PER_TILE 4
#define TILE_BYTES (ROWS_PER_TILE * ROWB)   // 51200
#define NTILES (Bn / ROWS_PER_TILE)         // 8192
#define NSTAGE 4

#define NTHREAD 512
#define NWARPS  (NTHREAD / 32)        // 16
#define NBLOCK  148

#define K_STRIDE 136                  // ints per K row (pad)
#define W_STRIDE 392                  // floats per weight group (3*128 + 8 pad)

// dynamic smem layout (bytes)
#define SM_STAGES 0
#define SM_W      (NSTAGE * TILE_BYTES)          // 204800
#define SM_K      (SM_W + 3 * W_STRIDE * 4)      // 209504
#define SM_V      (SM_K + Gn * K_STRIDE * 4)     // 223104
#define SM_BIAS   (SM_V + 80 * 4)                // 223424
#define SM_KBASE  (SM_BIAS + 16 * 4)             // 223488
#define SM_KFLAG  (SM_KBASE + 32 * 4)            // 223616
#define SM_MBAR   (SM_KFLAG + 32 * 4)            // 223744 (8-aligned)
#define SMEM_TOTAL (SM_MBAR + NSTAGE * 8)        // 223776

__device__ __forceinline__ uint32_t smem_u32(const void* p) {
    uint32_t a;
    asm("{ .reg .u64 t; cvta.to.shared.u64 t, %1; cvt.u32.u64 %0, t; }"
        : "=r"(a) : "l"(p));
    return a;
}

#define MBAR_INIT(mb, cnt) \
    asm volatile("mbarrier.init.shared.b64 [%0], %1;" :: "r"(mb), "r"(cnt) : "memory")

#define MBAR_EXPECT_TX(mb, bytes) \
    asm volatile("mbarrier.arrive.expect_tx.shared.b64 _, [%0], %1;" \
                 :: "r"(mb), "r"(bytes) : "memory")

#define BULK_G2S(dst, src, bytes, mb) \
    asm volatile("cp.async.bulk.shared::cta.global.mbarrier::complete_tx::bytes [%0], [%1], %2, [%3];" \
                 :: "r"(dst), "l"(src), "r"(bytes), "r"(mb) : "memory")

#define MBAR_WAIT(mb, ph) do {                                                   \
    uint32_t _done;                                                              \
    asm volatile("{\n\t.reg .pred p;\n\t"                                        \
        "mbarrier.try_wait.parity.acquire.cta.shared::cta.b64 p, [%1], %2;\n\t"  \
        "selp.b32 %0, 1, 0, p;\n\t}"                                             \
        : "=r"(_done) : "r"(mb), "r"(ph) : "memory");                            \
    if (!_done) {                                                                \
        asm volatile("{\n\t.reg .pred P1;\n\t"                                   \
            "W_%=:\n\t"                                                          \
            "mbarrier.try_wait.parity.acquire.cta.shared::cta.b64 P1, [%0], %1, 0x989680;\n\t" \
            "@P1 bra.uni D_%=;\n\t"                                              \
            "bra.uni W_%=;\n\t"                                                  \
            "D_%=:\n\t}" :: "r"(mb), "r"(ph) : "memory");                        \
    }                                                                            \
} while (0)

__global__ __launch_bounds__(NTHREAD, 1)
void mlp_rsna9_kernel(const float* __restrict__ x,
                      const int*   __restrict__ Kp,
                      const int*   __restrict__ Vp,
                      const float* __restrict__ Wsp, const float* __restrict__ bsp,
                      const float* __restrict__ Wnf, const float* __restrict__ bnf,
                      const float* __restrict__ Wss, const float* __restrict__ bss,
                      float* __restrict__ out)
{
    extern __shared__ __align__(128) char smem[];
    float* W_s    = reinterpret_cast<float*>(smem + SM_W);
    int*   K_s    = reinterpret_cast<int*>  (smem + SM_K);
    int*   V_s    = reinterpret_cast<int*>  (smem + SM_V);
    float* bias_s = reinterpret_cast<float*>(smem + SM_BIAS);
    int*   Kbase_s= reinterpret_cast<int*>  (smem + SM_KBASE);
    int*   Kflag_s= reinterpret_cast<int*>  (smem + SM_KFLAG);
    const uint32_t smb = smem_u32(smem);

    const int tid = threadIdx.x;

    // ---- stage K ----
    for (int idx = tid; idx < Gn * INn; idx += NTHREAD) {
        int g = idx >> 7, i = idx & 127;
        K_s[g * K_STRIDE + i] = Kp[idx];
    }
    // ---- stage W transposed: W_s[grp][c][i] = Wgrp[i*3 + c] ----
    for (int idx = tid; idx < 3 * NCn * INn; idx += NTHREAD) {
        int grp = idx / (NCn * INn);
        int rem = idx - grp * (NCn * INn);
        int c = rem >> 7, i = rem & 127;
        const float* Wg = (grp == 0) ? Wsp : (grp == 1) ? Wnf : Wss;
        W_s[grp * W_STRIDE + c * INn + i] = Wg[i * NCn + c];
    }
    if (tid < OUTn) V_s[tid] = Vp[tid];
    if (tid < 9) {
        int grp = tid / 3, c = tid - grp * 3;
        const float* bg = (grp == 0) ? bsp : (grp == 1) ? bnf : bss;
        bias_s[tid] = bg[c];
    }
    if (tid == 0) {
        #pragma unroll
        for (int s = 0; s < NSTAGE; s++) MBAR_INIT(smb + SM_MBAR + s * 8, 1);
    }
    __syncthreads();

    // ---- per-row contiguity check (enables float4 fast path) ----
    if (tid < Gn) {
        const int* Krow = K_s + tid * K_STRIDE;
        int base = Krow[0];
        int ok = ((base & 3) == 0) ? 1 : 0;
        #pragma unroll 8
        for (int i = 1; i < INn; i++) ok &= (Krow[i] == base + i) ? 1 : 0;
        Kbase_s[tid] = base;
        Kflag_s[tid] = ok;
    }
    __syncthreads();

    const int bx = blockIdx.x;
    const int nj = (NTILES - bx + NBLOCK - 1) / NBLOCK;   // my tile count

    // ---- prologue: fill pipeline ----
    if (tid == 0) {
        int pmax = (nj < NSTAGE) ? nj : NSTAGE;
        for (int j = 0; j < pmax; j++) {
            int tile = bx + j * NBLOCK;
            uint32_t s  = j & (NSTAGE - 1);
            uint32_t mb = smb + SM_MBAR + s * 8;
            MBAR_EXPECT_TX(mb, TILE_BYTES);
            BULK_G2S(smb + s * TILE_BYTES,
                     (const char*)x + (size_t)tile * TILE_BYTES,
                     (uint32_t)TILE_BYTES, mb);
        }
    }

    const int lane = tid & 31;
    const int warp = tid >> 5;
    const int sub  = lane & 7;     // position within 8-lane group
    const int q    = lane >> 3;    // row within tile (0..3)

    for (int j = 0; j < nj; j++) {
        const int tile = bx + j * NBLOCK;
        const int s    = j & (NSTAGE - 1);
        const uint32_t ph = (uint32_t)((j >> 2) & 1);
        MBAR_WAIT(smb + SM_MBAR + s * 8, ph);

        const float* stagep = reinterpret_cast<const float*>(smem + (size_t)s * TILE_BYTES);
        const float* myrow  = stagep + q * ROWF;
        const int    b0     = tile * ROWS_PER_TILE;

        for (int g = warp; g < Gn; g += NWARPS) {
            const int grp = (g < 5) ? 0 : (g < 15) ? 1 : 2;
            float s0 = 0.f, s1 = 0.f, s2 = 0.f;

            if (Kflag_s[g]) {
                const float4* xv4 = reinterpret_cast<const float4*>(myrow + Kbase_s[g]);
                const float4* w4  = reinterpret_cast<const float4*>(W_s + grp * W_STRIDE);
                #pragma unroll
                for (int t = 0; t < 4; t++) {
                    const int f = sub + 8 * t;
                    const float4 xv = xv4[f];
                    const float4 wa = w4[f];
                    const float4 wb = w4[32 + f];
                    const float4 wc = w4[64 + f];
                    s0 = fmaf(xv.x, wa.x, s0); s0 = fmaf(xv.y, wa.y, s0);
                    s0 = fmaf(xv.z, wa.z, s0); s0 = fmaf(xv.w, wa.w, s0);
                    s1 = fmaf(xv.x, wb.x, s1); s1 = fmaf(xv.y, wb.y, s1);
                    s1 = fmaf(xv.z, wb.z, s1); s1 = fmaf(xv.w, wb.w, s1);
                    s2 = fmaf(xv.x, wc.x, s2); s2 = fmaf(xv.y, wc.y, s2);
                    s2 = fmaf(xv.z, wc.z, s2); s2 = fmaf(xv.w, wc.w, s2);
                }
            } else {
                // honest gather via K (indexes within the row; full row in smem)
                const int*   Krow = K_s + g * K_STRIDE;
                const float* w0   = W_s + grp * W_STRIDE;
                #pragma unroll
                for (int t = 0; t < 16; t++) {
                    const int i  = sub + 8 * t;
                    const int kv = Krow[i];
                    const float xv = myrow[kv];
                    s0 = fmaf(xv, w0[i],           s0);
                    s1 = fmaf(xv, w0[INn   + i],   s1);
                    s2 = fmaf(xv, w0[2*INn + i],   s2);
                }
            }

            #pragma unroll
            for (int m = 4; m >= 1; m >>= 1) {
                s0 += __shfl_xor_sync(0xffffffffu, s0, m);
                s1 += __shfl_xor_sync(0xffffffffu, s1, m);
                s2 += __shfl_xor_sync(0xffffffffu, s2, m);
            }

            if (sub < NCn) {
                float v = (sub == 0) ? s0 : (sub == 1) ? s1 : s2;
                v += bias_s[grp * 3 + sub];
                out[(size_t)(b0 + q) * OUTn + V_s[g * NCn + sub]] = v;
            }
        }

        __syncthreads();   // stage s fully consumed by all warps

        if (tid == 0 && j + NSTAGE < nj) {
            int jn = j + NSTAGE;
            int tn = bx + jn * NBLOCK;
            uint32_t mb = smb + SM_MBAR + s * 8;
            MBAR_EXPECT_TX(mb, TILE_BYTES);
            BULK_G2S(smb + s * TILE_BYTES,
                     (const char*)x + (size_t)tn * TILE_BYTES,
                     (uint32_t)TILE_BYTES, mb);
        }
    }
}

extern "C" void kernel_launch(void* const* d_in, const int* in_sizes, int n_in,
                              void* d_out, int out_size)
{
    const float* x   = (const float*)d_in[0];
    const int*   K   = (const int*)  d_in[1];
    const int*   V   = (const int*)  d_in[2];
    const float* Wsp = (const float*)d_in[3];
    const float* bsp = (const float*)d_in[4];
    const float* Wnf = (const float*)d_in[5];
    const float* bnf = (const float*)d_in[6];
    const float* Wss = (const float*)d_in[7];
    const float* bss = (const float*)d_in[8];
    float* out = (float*)d_out;

    static int smem_set = 0;
    if (!smem_set) {
        cudaFuncSetAttribute(mlp_rsna9_kernel,
                             cudaFuncAttributeMaxDynamicSharedMemorySize, SMEM_TOTAL);
        smem_set = 1;
    }
    mlp_rsna9_kernel<<<NBLOCK, NTHREAD, SMEM_TOTAL>>>(x, K, V, Wsp, bsp, Wnf, bnf, Wss, bss, out);
}

// round 6
// speedup vs baseline: 1.2581x; 1.2581x over previous
#include <cuda_runtime.h>
#include <cstdint>

// Problem constants
#define Bn    32768
#define Gn    25
#define INn   128
#define NCn   3
#define OUTn  75
#define ROWW  (Gn * INn)          // 3200 floats per x row
#define BQ    (Bn / 4)            // 8192 b-quads per g
#define QUADS (Gn * BQ)           // 204800 (same-g, 4 consecutive b)
#define PAIRS (QUADS / 2)         // 102400

#define K_STRIDE 136              // ints per K row (pad)
#define W_STRIDE 392              // floats per weight group (3*128 + 8 pad)

#define NBLOCK 2048
#define NTHREAD 256

// Batched 16B non-coherent global load. volatile => ptxas cannot tear the
// batch apart or sink individual loads down to their first use.
__device__ __forceinline__ float4 ldg128(const float4* p) {
    float4 v;
    asm volatile("ld.global.nc.v4.f32 {%0,%1,%2,%3}, [%4];"
                 : "=f"(v.x), "=f"(v.y), "=f"(v.z), "=f"(v.w)
                 : "l"(p));
    return v;
}

__global__ __launch_bounds__(NTHREAD)
void mlp_rsna9_kernel(const float* __restrict__ x,
                      const int*   __restrict__ Kp,
                      const int*   __restrict__ Vp,
                      const float* __restrict__ Wsp, const float* __restrict__ bsp,
                      const float* __restrict__ Wnf, const float* __restrict__ bnf,
                      const float* __restrict__ Wss, const float* __restrict__ bss,
                      float* __restrict__ out)
{
    __shared__ int   K_s[Gn * K_STRIDE];
    __shared__ __align__(16) float W_s[3 * W_STRIDE]; // grp*392 + c*128 + i
    __shared__ int   V_s[OUTn + 1];
    __shared__ float bias_s[12];
    __shared__ int   Kbase_s[Gn];
    __shared__ int   Kflag_s[Gn];

    const int tid = threadIdx.x;

    // ---- stage K ----
    for (int idx = tid; idx < Gn * INn; idx += NTHREAD) {
        int g = idx >> 7, i = idx & 127;
        K_s[g * K_STRIDE + i] = Kp[idx];
    }
    // ---- stage W transposed: W_s[grp][c][i] = Wgrp[i*3 + c] ----
    for (int idx = tid; idx < 3 * NCn * INn; idx += NTHREAD) {
        int grp = idx / (NCn * INn);
        int rem = idx - grp * (NCn * INn);
        int c = rem >> 7, i = rem & 127;
        const float* Wg = (grp == 0) ? Wsp : (grp == 1) ? Wnf : Wss;
        W_s[grp * W_STRIDE + c * INn + i] = Wg[i * NCn + c];
    }
    if (tid < OUTn) V_s[tid] = Vp[tid];
    if (tid < 9) {
        int grp = tid / 3, c = tid - grp * 3;
        const float* bg = (grp == 0) ? bsp : (grp == 1) ? bnf : bss;
        bias_s[tid] = bg[c];
    }
    __syncthreads();

    // ---- per-row contiguity check (enables float4 fast path) ----
    if (tid < Gn) {
        const int* Krow = K_s + tid * K_STRIDE;
        int base = Krow[0];
        int ok = ((base & 3) == 0) ? 1 : 0;
        #pragma unroll 8
        for (int i = 1; i < INn; i++) ok &= (Krow[i] == base + i) ? 1 : 0;
        Kbase_s[tid] = base;
        Kflag_s[tid] = ok;
    }
    __syncthreads();

    const int lane = tid & 31;
    const int warp = tid >> 5;
    const int sub  = lane & 7;     // position within 8-lane task group
    const int q    = lane >> 3;    // which of 4 b's in a quad

    const int warp_global = blockIdx.x * (NTHREAD / 32) + warp;
    const int total_warps = gridDim.x * (NTHREAD / 32);

    for (int pp = warp_global; pp < PAIRS; pp += total_warps) {
        const int qq  = pp * 2;                // first quad of the pair
        const int g   = qq >> 13;              // / 8192 (same g, both quads)
        const int bq  = qq & (BQ - 1);
        const int bA  = (bq    ) * 4 + q;
        const int bB  = (bq + 1) * 4 + q;
        const int grp = (g < 5) ? 0 : (g < 15) ? 1 : 2;

        float a0 = 0.f, a1 = 0.f, a2 = 0.f;
        float c0 = 0.f, c1 = 0.f, c2 = 0.f;

        if (Kflag_s[g]) {
            const int base = Kbase_s[g];
            const float4* xA = reinterpret_cast<const float4*>(x + (size_t)bA * ROWW + base);
            const float4* xB = reinterpret_cast<const float4*>(x + (size_t)bB * ROWW + base);
            const float4* w4 = reinterpret_cast<const float4*>(W_s + grp * W_STRIDE);

            // ---- PHASE 1: issue ALL 8 global loads back-to-back ----
            float4 va0 = ldg128(xA + sub);
            float4 va1 = ldg128(xA + sub + 8);
            float4 va2 = ldg128(xA + sub + 16);
            float4 va3 = ldg128(xA + sub + 24);
            float4 vb0 = ldg128(xB + sub);
            float4 vb1 = ldg128(xB + sub + 8);
            float4 vb2 = ldg128(xB + sub + 16);
            float4 vb3 = ldg128(xB + sub + 24);

            // ---- PHASE 2: compute (weights broadcast from smem) ----
            #pragma unroll
            for (int t = 0; t < 4; t++) {
                const int f = sub + 8 * t;
                const float4 w0 = w4[f];
                const float4 w1 = w4[32 + f];
                const float4 w2 = w4[64 + f];
                const float4 va = (t == 0) ? va0 : (t == 1) ? va1 : (t == 2) ? va2 : va3;
                const float4 vb = (t == 0) ? vb0 : (t == 1) ? vb1 : (t == 2) ? vb2 : vb3;
                a0 = fmaf(va.x, w0.x, a0); a0 = fmaf(va.y, w0.y, a0);
                a0 = fmaf(va.z, w0.z, a0); a0 = fmaf(va.w, w0.w, a0);
                a1 = fmaf(va.x, w1.x, a1); a1 = fmaf(va.y, w1.y, a1);
                a1 = fmaf(va.z, w1.z, a1); a1 = fmaf(va.w, w1.w, a1);
                a2 = fmaf(va.x, w2.x, a2); a2 = fmaf(va.y, w2.y, a2);
                a2 = fmaf(va.z, w2.z, a2); a2 = fmaf(va.w, w2.w, a2);
                c0 = fmaf(vb.x, w0.x, c0); c0 = fmaf(vb.y, w0.y, c0);
                c0 = fmaf(vb.z, w0.z, c0); c0 = fmaf(vb.w, w0.w, c0);
                c1 = fmaf(vb.x, w1.x, c1); c1 = fmaf(vb.y, w1.y, c1);
                c1 = fmaf(vb.z, w1.z, c1); c1 = fmaf(vb.w, w1.w, c1);
                c2 = fmaf(vb.x, w2.x, c2); c2 = fmaf(vb.y, w2.y, c2);
                c2 = fmaf(vb.z, w2.z, c2); c2 = fmaf(vb.w, w2.w, c2);
            }
        } else {
            // ---- fallback: honest gather via K ----
            const float* xAr  = x + (size_t)bA * ROWW;
            const float* xBr  = x + (size_t)bB * ROWW;
            const int*   Krow = K_s + g * K_STRIDE;
            const float* w0   = W_s + grp * W_STRIDE;
            #pragma unroll
            for (int t = 0; t < 16; t++) {
                const int i  = sub + 8 * t;
                const int kv = Krow[i];
                const float va = __ldg(xAr + kv);
                const float vb = __ldg(xBr + kv);
                const float wa = w0[i], wb = w0[INn + i], wc = w0[2*INn + i];
                a0 = fmaf(va, wa, a0); a1 = fmaf(va, wb, a1); a2 = fmaf(va, wc, a2);
                c0 = fmaf(vb, wa, c0); c1 = fmaf(vb, wb, c1); c2 = fmaf(vb, wc, c2);
            }
        }

        // butterfly reduction within each 8-lane group
        #pragma unroll
        for (int m = 4; m >= 1; m >>= 1) {
            a0 += __shfl_xor_sync(0xffffffffu, a0, m);
            a1 += __shfl_xor_sync(0xffffffffu, a1, m);
            a2 += __shfl_xor_sync(0xffffffffu, a2, m);
            c0 += __shfl_xor_sync(0xffffffffu, c0, m);
            c1 += __shfl_xor_sync(0xffffffffu, c1, m);
            c2 += __shfl_xor_sync(0xffffffffu, c2, m);
        }

        if (sub < NCn) {
            const int vcol = V_s[g * NCn + sub];
            const float bia = bias_s[grp * 3 + sub];
            float sa = (sub == 0) ? a0 : (sub == 1) ? a1 : a2;
            float sb = (sub == 0) ? c0 : (sub == 1) ? c1 : c2;
            out[(size_t)bA * OUTn + vcol] = sa + bia;
            out[(size_t)bB * OUTn + vcol] = sb + bia;
        }
    }
}

extern "C" void kernel_launch(void* const* d_in, const int* in_sizes, int n_in,
                              void* d_out, int out_size)
{
    const float* x   = (const float*)d_in[0];
    const int*   K   = (const int*)  d_in[1];
    const int*   V   = (const int*)  d_in[2];
    const float* Wsp = (const float*)d_in[3];
    const float* bsp = (const float*)d_in[4];
    const float* Wnf = (const float*)d_in[5];
    const float* bnf = (const float*)d_in[6];
    const float* Wss = (const float*)d_in[7];
    const float* bss = (const float*)d_in[8];
    float* out = (float*)d_out;

    mlp_rsna9_kernel<<<NBLOCK, NTHREAD>>>(x, K, V, Wsp, bsp, Wnf, bnf, Wss, bss, out);
}

// round 8
// speedup vs baseline: 1.4947x; 1.1881x over previous
#include <cuda_runtime.h>
#include <cstdint>

// Problem constants
#define Bn    32768
#define Gn    25
#define INn   128
#define NCn   3
#define OUTn  75
#define ROWW  (Gn * INn)          // 3200 floats per x row
#define MB    (Bn / 8)            // 4096 8-row bands
#define PAIRS (MB * Gn)           // 102400 pairs: pair = (band m, group g)

#define K_STRIDE 136              // ints per K row (pad)
#define W_STRIDE 392              // floats per weight group (3*128 + 8 pad)

#define NBLOCK 2048
#define NTHREAD 256

__global__ __launch_bounds__(NTHREAD, 6)
void mlp_rsna9_kernel(const float* __restrict__ x,
                      const int*   __restrict__ Kp,
                      const int*   __restrict__ Vp,
                      const float* __restrict__ Wsp, const float* __restrict__ bsp,
                      const float* __restrict__ Wnf, const float* __restrict__ bnf,
                      const float* __restrict__ Wss, const float* __restrict__ bss,
                      float* __restrict__ out)
{
    __shared__ int   K_s[Gn * K_STRIDE];
    __shared__ __align__(16) float W_s[3 * W_STRIDE]; // grp*392 + c*128 + i
    __shared__ int   V_s[OUTn + 1];
    __shared__ float bias_s[12];
    __shared__ int   Kbase_s[Gn];
    __shared__ int   Kflag_s[Gn];

    const int tid = threadIdx.x;

    // ---- stage K ----
    for (int idx = tid; idx < Gn * INn; idx += NTHREAD) {
        int g = idx >> 7, i = idx & 127;
        K_s[g * K_STRIDE + i] = Kp[idx];
    }
    // ---- stage W transposed: W_s[grp][c][i] = Wgrp[i*3 + c] ----
    for (int idx = tid; idx < 3 * NCn * INn; idx += NTHREAD) {
        int grp = idx / (NCn * INn);
        int rem = idx - grp * (NCn * INn);
        int c = rem >> 7, i = rem & 127;
        const float* Wg = (grp == 0) ? Wsp : (grp == 1) ? Wnf : Wss;
        W_s[grp * W_STRIDE + c * INn + i] = Wg[i * NCn + c];
    }
    if (tid < OUTn) V_s[tid] = Vp[tid];
    if (tid < 9) {
        int grp = tid / 3, c = tid - grp * 3;
        const float* bg = (grp == 0) ? bsp : (grp == 1) ? bnf : bss;
        bias_s[tid] = bg[c];
    }
    __syncthreads();

    // ---- per-row contiguity check (enables float4 fast path) ----
    if (tid < Gn) {
        const int* Krow = K_s + tid * K_STRIDE;
        int base = Krow[0];
        int ok = ((base & 3) == 0) ? 1 : 0;
        #pragma unroll 8
        for (int i = 1; i < INn; i++) ok &= (Krow[i] == base + i) ? 1 : 0;
        Kbase_s[tid] = base;
        Kflag_s[tid] = ok;
    }
    __syncthreads();

    const int lane = tid & 31;
    const int warp = tid >> 5;
    const int sub  = lane & 7;     // position within 8-lane task group
    const int q    = lane >> 3;    // which of 4 b's in a quad

    const int warp_global = blockIdx.x * (NTHREAD / 32) + warp;
    const int total_warps = gridDim.x * (NTHREAD / 32);

    for (int pp = warp_global; pp < PAIRS; pp += total_warps) {
        // m-major ordering: consecutive pairs share an 8-row band
        const int m   = pp / Gn;               // 8-row band (0..4095)
        const int g   = pp - m * Gn;           // group (0..24)
        const int bA  = m * 8 + q;             // rows m*8 .. m*8+3
        const int bB  = bA + 4;                // rows m*8+4 .. m*8+7
        const int grp = (g < 5) ? 0 : (g < 15) ? 1 : 2;

        float a0 = 0.f, a1 = 0.f, a2 = 0.f;
        float c0 = 0.f, c1 = 0.f, c2 = 0.f;

        if (Kflag_s[g]) {
            const int base = Kbase_s[g];
            const float4* xA = reinterpret_cast<const float4*>(x + (size_t)bA * ROWW + base);
            const float4* xB = reinterpret_cast<const float4*>(x + (size_t)bB * ROWW + base);
            const float4* w4 = reinterpret_cast<const float4*>(W_s + grp * W_STRIDE);
            #pragma unroll
            for (int t = 0; t < 4; t++) {
                const int f = sub + 8 * t;            // same across q -> W broadcast
                const float4 va = __ldg(xA + f);
                const float4 vb = __ldg(xB + f);
                const float4 w0 = w4[f];
                const float4 w1 = w4[32 + f];
                const float4 w2 = w4[64 + f];
                a0 = fmaf(va.x, w0.x, a0); a0 = fmaf(va.y, w0.y, a0);
                a0 = fmaf(va.z, w0.z, a0); a0 = fmaf(va.w, w0.w, a0);
                a1 = fmaf(va.x, w1.x, a1); a1 = fmaf(va.y, w1.y, a1);
                a1 = fmaf(va.z, w1.z, a1); a1 = fmaf(va.w, w1.w, a1);
                a2 = fmaf(va.x, w2.x, a2); a2 = fmaf(va.y, w2.y, a2);
                a2 = fmaf(va.z, w2.z, a2); a2 = fmaf(va.w, w2.w, a2);
                c0 = fmaf(vb.x, w0.x, c0); c0 = fmaf(vb.y, w0.y, c0);
                c0 = fmaf(vb.z, w0.z, c0); c0 = fmaf(vb.w, w0.w, c0);
                c1 = fmaf(vb.x, w1.x, c1); c1 = fmaf(vb.y, w1.y, c1);
                c1 = fmaf(vb.z, w1.z, c1); c1 = fmaf(vb.w, w1.w, c1);
                c2 = fmaf(vb.x, w2.x, c2); c2 = fmaf(vb.y, w2.y, c2);
                c2 = fmaf(vb.z, w2.z, c2); c2 = fmaf(vb.w, w2.w, c2);
            }
        } else {
            // ---- fallback: honest gather via K ----
            const float* xAr  = x + (size_t)bA * ROWW;
            const float* xBr  = x + (size_t)bB * ROWW;
            const int*   Krow = K_s + g * K_STRIDE;
            const float* w0   = W_s + grp * W_STRIDE;
            #pragma unroll
            for (int t = 0; t < 16; t++) {
                const int i  = sub + 8 * t;
                const int kv = Krow[i];
                const float va = __ldg(xAr + kv);
                const float vb = __ldg(xBr + kv);
                const float wa = w0[i], wb = w0[INn + i], wc = w0[2*INn + i];
                a0 = fmaf(va, wa, a0); a1 = fmaf(va, wb, a1); a2 = fmaf(va, wc, a2);
                c0 = fmaf(vb, wa, c0); c1 = fmaf(vb, wb, c1); c2 = fmaf(vb, wc, c2);
            }
        }

        // butterfly reduction within each 8-lane group
        #pragma unroll
        for (int m2 = 4; m2 >= 1; m2 >>= 1) {
            a0 += __shfl_xor_sync(0xffffffffu, a0, m2);
            a1 += __shfl_xor_sync(0xffffffffu, a1, m2);
            a2 += __shfl_xor_sync(0xffffffffu, a2, m2);
            c0 += __shfl_xor_sync(0xffffffffu, c0, m2);
            c1 += __shfl_xor_sync(0xffffffffu, c1, m2);
            c2 += __shfl_xor_sync(0xffffffffu, c2, m2);
        }

        if (sub < NCn) {
            const int vcol = V_s[g * NCn + sub];
            const float bia = bias_s[grp * 3 + sub];
            float sa = (sub == 0) ? a0 : (sub == 1) ? a1 : a2;
            float sb = (sub == 0) ? c0 : (sub == 1) ? c1 : c2;
            out[(size_t)bA * OUTn + vcol] = sa + bia;
            out[(size_t)bB * OUTn + vcol] = sb + bia;
        }
    }
}

extern "C" void kernel_launch(void* const* d_in, const int* in_sizes, int n_in,
                              void* d_out, int out_size)
{
    const float* x   = (const float*)d_in[0];
    const int*   K   = (const int*)  d_in[1];
    const int*   V   = (const int*)  d_in[2];
    const float* Wsp = (const float*)d_in[3];
    const float* bsp = (const float*)d_in[4];
    const float* Wnf = (const float*)d_in[5];
    const float* bnf = (const float*)d_in[6];
    const float* Wss = (const float*)d_in[7];
    const float* bss = (const float*)d_in[8];
    float* out = (float*)d_out;

    mlp_rsna9_kernel<<<NBLOCK, NTHREAD>>>(x, K, V, Wsp, bsp, Wnf, bnf, Wss, bss, out);
}